// round 17
// baseline (speedup 1.0000x reference)
#include <cuda_runtime.h>

typedef unsigned int u32;
typedef unsigned long long u64;

// EXACT int8-TC GEMM: xin[800,100] = x[800,460800] @ w_in[100,460800]^T.
// 4-limb balanced base-128 quantization (exact for these ranges), 10 integer
// product groups (i+j<=3) in s32 (no rounding), fp64 combine. R16 proved the
// numerics (rel_err 1.02e-7 floor); this round removes register spill:
// 512 thr, warp tile m16n32 -> 64 accums/thread, W via cp.async.

#define F_K    460800L
#define NCHUNK 14400
#define SPLITS 11
#define CPS    1310
#define MT     64
#define NRT    13
#define NCOLW  128
#define NTHREADS 512

#define XPL    3072          // X plane: 64 rows x 48B
#define WOFF   12288
#define WPL    6144          // W plane: 128 rows x 48B
#define STAGE  36864
#define SMEM_TOTAL (2 * STAGE)   // 73728

// W limb planes, chunk-tiled: word = c*4096 + p*1024 + row*8 + q
__device__ __align__(16) u32 g_wl[(long)NCHUNK * 4096];   // 235.9 MB
__device__ float g_part[SPLITS * 800 * NCOLW];            // 4.5 MB
__device__ float g_xin[800 * 100];

__device__ __forceinline__ u32 smem_u32(const void* p) {
    u32 a;
    asm("{ .reg .u64 t; cvta.to.shared.u64 t, %1; cvt.u32.u64 %0, t; }" : "=r"(a) : "l"(p));
    return a;
}
__device__ __forceinline__ float rnif(float x) {
    float r; asm("cvt.rni.f32.f32 %0, %1;" : "=f"(r) : "f"(x)); return r;
}
__device__ __forceinline__ u32 prmt(u32 a, u32 b, u32 s) {
    u32 d; asm("prmt.b32 %0, %1, %2, %3;" : "=r"(d) : "r"(a), "r"(b), "r"(s)); return d;
}
__device__ __forceinline__ u32 lds32(u32 a) {
    u32 d; asm volatile("ld.shared.b32 %0, [%1];" : "=r"(d) : "r"(a)); return d;
}
__device__ __forceinline__ void cpasync16(u32 dst, const void* src) {
    asm volatile("cp.async.cg.shared.global [%0], [%1], 16;" :: "r"(dst), "l"(src) : "memory");
}
__device__ __forceinline__ void cp_commit() {
    asm volatile("cp.async.commit_group;" ::: "memory");
}
__device__ __forceinline__ void cp_wait0() {
    asm volatile("cp.async.wait_group 0;" ::: "memory");
}
__device__ __forceinline__ void mma_s8(int* c, const u32* a, u32 b0, u32 b1) {
    asm volatile(
        "mma.sync.aligned.m16n8k32.row.col.s32.s8.s8.s32 "
        "{%0,%1,%2,%3},{%4,%5,%6,%7},{%8,%9},{%0,%1,%2,%3};"
        : "+r"(c[0]), "+r"(c[1]), "+r"(c[2]), "+r"(c[3])
        : "r"(a[0]), "r"(a[1]), "r"(a[2]), "r"(a[3]), "r"(b0), "r"(b1));
}

// 4 balanced base-128 limbs of 4 floats, byte-packed per plane (exact repr).
__device__ __forceinline__ void limbs_pack(float4 v, float s0, u32 pk[4]) {
    float in[4] = {v.x, v.y, v.z, v.w};
    u32 li[4][4];
    const float i0 = 1.f / s0;
    const float s1 = s0 * 128.f, i1 = i0 * 0.0078125f;
    const float s2 = s1 * 128.f, i2 = i1 * 0.0078125f;
    const float s3 = s2 * 128.f;
#pragma unroll
    for (int e = 0; e < 4; e++) {
        float x = in[e];
        float f0 = rnif(x * s0); float r = fmaf(f0, -i0, x);
        float f1 = rnif(r * s1); r = fmaf(f1, -i1, r);
        float f2 = rnif(r * s2); r = fmaf(f2, -i2, r);
        float f3 = rnif(r * s3);
        li[0][e] = (u32)__float2int_rn(f0);
        li[1][e] = (u32)__float2int_rn(f1);
        li[2][e] = (u32)__float2int_rn(f2);
        li[3][e] = (u32)__float2int_rn(f3);
    }
#pragma unroll
    for (int p = 0; p < 4; p++) {
        u32 t01 = prmt(li[p][0], li[p][1], 0x0040);
        u32 t23 = prmt(li[p][2], li[p][3], 0x0040);
        pk[p] = prmt(t01, t23, 0x5410);
    }
}

// ---- kernel 1: W -> limb planes once (rows 100..127 zero) ----
__global__ __launch_bounds__(128) void wconv(const float* __restrict__ W) {
    const int c = blockIdx.x, tid = threadIdx.x;
#pragma unroll
    for (int j = 0; j < 8; j++) {
        int i = tid + j * 128;                     // 0..1023 = row*8+q
        int row = i >> 3, q = i & 7;
        u32 pk[4] = {0u, 0u, 0u, 0u};
        if (row < 100) {
            float4 v = *(const float4*)(W + (long)row * F_K + (long)c * 32 + q * 4);
            limbs_pack(v, 128.f, pk);              // w scale 2^7
        }
        long wi = (long)c * 4096 + i;
#pragma unroll
        for (int p = 0; p < 4; p++) g_wl[wi + p * 1024] = pk[p];
    }
}

// ---- kernel 2: exact s8 GEMM, no spill ----
__global__ __launch_bounds__(NTHREADS, 1) void gemm_s8(const float* __restrict__ X) {
    extern __shared__ __align__(16) char smem[];
    const u32 sb = smem_u32(smem);
    const int tid = threadIdx.x, lane = tid & 31, wid = tid >> 5;
    const int mw = wid & 3, nw = wid >> 2;         // 4 m-warps x 4 n-warps
    const int rt = blockIdx.x, sp = blockIdx.y;
    const int c0 = sp * CPS;
    const int ntiles = (sp == SPLITS - 1) ? (NCHUNK - c0) : CPS;

    int S[4][4][4];                                 // 64 s32 accumulators
#pragma unroll
    for (int g = 0; g < 4; g++)
#pragma unroll
        for (int t = 0; t < 4; t++)
#pragma unroll
            for (int j = 0; j < 4; j++) S[g][t][j] = 0;

    // X: 1 quad per thread (64 rows x 8 quads = 512)
    const int xrow = tid >> 3, xq = tid & 7;
    const long xoff = (long)min(rt * MT + xrow, 799) * F_K + (long)c0 * 32 + xq * 4;
    const u32 xsts = (u32)(xrow * 48 + xq * 4);
    // W cp.async: 2 x 16B chunks per thread (1024 total)
    u32 wdst[2]; u32 wso[2];
#pragma unroll
    for (int k = 0; k < 2; k++) {
        int j = tid + k * NTHREADS;                // chunk id < 1024
        int p = j >> 8, rem = j & 255, r = rem >> 1, h = rem & 1;
        wdst[k] = WOFF + p * WPL + r * 48 + h * 16;
        wso[k] = j * 16;                           // byte offset within chunk block
    }
    const char* wbase = (const char*)(g_wl + (long)c0 * 4096);

    // fragment addresses
    const u32 a_base = (16 * mw + (lane >> 2)) * 48 + 4 * (lane & 3);
    const u32 b_base = WOFF + (32 * nw + (lane >> 2)) * 48 + 4 * (lane & 3);

    // prologue: stage 0
    {
#pragma unroll
        for (int k = 0; k < 2; k++) cpasync16(sb + wdst[k], wbase + wso[k]);
        cp_commit();
        float4 xr = *(const float4*)(X + xoff);
        u32 pk[4];
        limbs_pack(xr, 16.f, pk);                  // x scale 2^4
#pragma unroll
        for (int p = 0; p < 4; p++) *(u32*)(smem + p * XPL + xsts) = pk[p];
        cp_wait0();
    }
    __syncthreads();

    float4 xr;
    for (int kt = 0; kt < ntiles; kt++) {
        const bool more = (kt + 1) < ntiles;
        const u32 cur = (u32)(kt & 1) * STAGE, nxt = (u32)((kt + 1) & 1) * STAGE;
        if (more) {
            const char* wnb = wbase + (long)(kt + 1) * 16384;
#pragma unroll
            for (int k = 0; k < 2; k++) cpasync16(sb + nxt + wdst[k], wnb + wso[k]);
            cp_commit();
            xr = *(const float4*)(X + xoff + (long)(kt + 1) * 32);
        }
        const u32 st = sb + cur;
        u32 a[4][4];
#pragma unroll
        for (int p = 0; p < 4; p++) {
            u32 ab = st + p * XPL + a_base;
            a[p][0] = lds32(ab);       a[p][1] = lds32(ab + 384);
            a[p][2] = lds32(ab + 16);  a[p][3] = lds32(ab + 400);
        }
#pragma unroll
        for (int tn = 0; tn < 4; tn++) {
            u32 b[4][2];
#pragma unroll
            for (int p = 0; p < 4; p++) {
                u32 bb = st + p * WPL + b_base + tn * (8 * 48);
                b[p][0] = lds32(bb); b[p][1] = lds32(bb + 16);
            }
            mma_s8(S[0][tn], a[0], b[0][0], b[0][1]);      // g0
            mma_s8(S[1][tn], a[0], b[1][0], b[1][1]);      // g1
            mma_s8(S[1][tn], a[1], b[0][0], b[0][1]);
            mma_s8(S[2][tn], a[0], b[2][0], b[2][1]);      // g2
            mma_s8(S[2][tn], a[1], b[1][0], b[1][1]);
            mma_s8(S[2][tn], a[2], b[0][0], b[0][1]);
            mma_s8(S[3][tn], a[0], b[3][0], b[3][1]);      // g3
            mma_s8(S[3][tn], a[1], b[2][0], b[2][1]);
            mma_s8(S[3][tn], a[2], b[1][0], b[1][1]);
            mma_s8(S[3][tn], a[3], b[0][0], b[0][1]);
        }
        if (more) {
            u32 pk[4];
            limbs_pack(xr, 16.f, pk);
#pragma unroll
            for (int p = 0; p < 4; p++) *(u32*)(smem + nxt + p * XPL + xsts) = pk[p];
            cp_wait0();
        }
        __syncthreads();
    }

    // epilogue: exact fp64 combine; value = (G0+(G1+(G2+G3/128)/128)/128)/2048
    const int r0 = rt * MT + 16 * mw + (lane >> 2);
    const int colb = 32 * nw + 2 * (lane & 3);
#pragma unroll
    for (int tn = 0; tn < 4; tn++) {
        int col = colb + 8 * tn;
#pragma unroll
        for (int h = 0; h < 2; h++) {
            int row = r0 + 8 * h;
            if (row < 800) {
#pragma unroll
                for (int e = 0; e < 2; e++) {
                    double d = (double)S[3][tn][2 * h + e];
                    d = d * 0.0078125 + (double)S[2][tn][2 * h + e];
                    d = d * 0.0078125 + (double)S[1][tn][2 * h + e];
                    d = d * 0.0078125 + (double)S[0][tn][2 * h + e];
                    g_part[((long)sp * 800 + row) * NCOLW + col + e] =
                        (float)(d * 4.8828125e-4);
                }
            }
        }
    }
}

// ---- kernel 3: deterministic split-K reduce in fp64 ----
__global__ void reduce_kernel() {
    int row = blockIdx.x, c = threadIdx.x;
    if (c >= 100) return;
    double s = 0.0;
    for (int sp = 0; sp < SPLITS; sp++)
        s += (double)g_part[((long)sp * 800 + row) * NCOLW + c];
    g_xin[row * 100 + c] = (float)s;
}

// ---- kernel 4: per-batch LIF/LI scan (proven) ----
__global__ __launch_bounds__(128) void scan_kernel(const float* __restrict__ wrec,
                                                   const float* __restrict__ wout,
                                                   float* __restrict__ out) {
    __shared__ float sw[10000];
    __shared__ float so[600];
    __shared__ float zs[100];
    const int b = blockIdx.x, tid = threadIdx.x;
    for (int i = tid; i < 10000; i += 128) sw[i] = wrec[i];
    for (int i = tid; i < 600; i += 128) so[i] = wout[i];
    if (tid < 100) zs[tid] = 0.f;
    float v = 0.f, ii = 0.f, vo = 0.f, io = 0.f;
    __syncthreads();

    for (int t = 0; t < 50; t++) {
        float zn = 0.f, inew = 0.f, vnew = 0.f;
        if (tid < 100) {
            float rec = 0.f;                       // recurrent uses OLD z
            for (int j = 0; j < 100; j++) rec += zs[j] * sw[tid * 100 + j];
            float vd = v + 0.1f * (ii - v);
            float id = 0.9f * ii;
            zn = (vd - 0.3f > 0.f) ? 1.f : 0.f;
            vnew = (1.f - zn) * vd;
            inew = id + g_xin[(t * 16 + b) * 100 + tid] + rec;
        }
        __syncthreads();
        if (tid < 100) { zs[tid] = zn; v = vnew; ii = inew; }
        __syncthreads();
        if (tid < 6) {
            float y = 0.f;
            for (int h = 0; h < 100; h++) y += zs[h] * so[tid * 100 + h];
            float von = vo + 0.1f * (io - vo);
            io = 0.8f * io + y;
            vo = von;
            out[(t * 16 + b) * 6 + tid] = von;
        }
        __syncthreads();
    }
}

extern "C" void kernel_launch(void* const* d_in, const int* in_sizes, int n_in,
                              void* d_out, int out_size) {
    const float *x = 0, *win = 0, *wrec = 0, *wout = 0;
    for (int i = 0; i < n_in; i++) {
        if (in_sizes[i] == 368640000) x = (const float*)d_in[i];
        else if (in_sizes[i] == 46080000) win = (const float*)d_in[i];
        else if (in_sizes[i] == 10000) wrec = (const float*)d_in[i];
        else if (in_sizes[i] == 600) wout = (const float*)d_in[i];
    }
    cudaFuncSetAttribute(gemm_s8, cudaFuncAttributeMaxDynamicSharedMemorySize, SMEM_TOTAL);
    wconv<<<NCHUNK, 128>>>(win);
    gemm_s8<<<dim3(NRT, SPLITS), NTHREADS, SMEM_TOTAL>>>(x);
    reduce_kernel<<<800, 128>>>();
    scan_kernel<<<16, 128>>>(wrec, wout, (float*)d_out);
}